// round 11
// baseline (speedup 1.0000x reference)
#include <cuda_runtime.h>
#include <cuda_bf16.h>
#include <cstdint>

// Problem dims (fixed by reference)
#define T_DIM 1024
#define B_DIM 32
#define K_DIM 8
#define N_DIM 64
#define M_DIM 64
#define KN    512      // K_DIM * N_DIM
#define BK    256      // B_DIM * K_DIM
#define ROWS  32768    // T*B rows of the big GEMM
#define KTOT  1024     // real K
#define NTOT  128      // output cols (re|im stacked)

#define X_SZ   (T_DIM * B_DIM * K_DIM)   // 262144
#define C_SZ   (K_DIM * N_DIM * M_DIM)   // 32768
#define V_SZ   (K_DIM * N_DIM)           // 512
#define OUT_CPLX (T_DIM * B_DIM * M_DIM) // 2097152 complex values

// ---------------- scratch (static device allocations only) ----------------
__device__ float2   g_Bp[KN];
// A: [row][kc 0..31][np 0..31] with within-chunk permutation np(oc):
//   np = (oc>>3)*8 + 2*(oc&3) + ((oc>>2)&1)  (so (kk, kk+4) become adjacent)
__device__ float    g_Af[(size_t)ROWS * 1024];          // 128 MiB tf32-rounded
// B: fragment-major [kc][nb][kp][lane][w]: w0=b0(ks=2kp) w1=b1(2kp) w2=b0(2kp+1) w3=b1(2kp+1)
__device__ uint32_t g_Bf[32 * 16 * 2 * 32 * 4];         // 512 KiB

// ---------------- PTX helpers (base sm_100 features only) ----------------
__device__ __forceinline__ uint32_t smem_u32(const void* p) {
    uint32_t a;
    asm("{ .reg .u64 t; cvta.to.shared.u64 t, %1; cvt.u32.u64 %0, t; }" : "=r"(a) : "l"(p));
    return a;
}
__device__ __forceinline__ uint32_t f2tf32(float f) {
    uint32_t u;
    asm("cvt.rna.tf32.f32 %0, %1;" : "=r"(u) : "f"(f));
    return u;
}
__device__ __forceinline__ void mma_tf32(float* d, const uint32_t* a, const uint32_t* b) {
    asm volatile("mma.sync.aligned.m16n8k8.row.col.f32.tf32.tf32.f32 "
                 "{%0,%1,%2,%3}, {%4,%5,%6,%7}, {%8,%9}, {%0,%1,%2,%3};"
                 : "+f"(d[0]), "+f"(d[1]), "+f"(d[2]), "+f"(d[3])
                 : "r"(a[0]), "r"(a[1]), "r"(a[2]), "r"(a[3]), "r"(b[0]), "r"(b[1]));
}
#define CP16(dst, src) \
    asm volatile("cp.async.cg.shared.global [%0], [%1], 16;" :: "r"(dst), "l"(src))
#define CP_COMMIT() asm volatile("cp.async.commit_group;" ::: "memory")
#define CP_WAIT(n)  asm volatile("cp.async.wait_group %0;" :: "n"(n) : "memory")

// ---------------- kernel 1: B' from lambda (fp32, parallel) ---------------
__global__ void bp_kernel(const float* __restrict__ lam_re,
                          const float* __restrict__ lam_im) {
    __shared__ float ssr[64], ssi[64];
    int idx = blockIdx.x;
    int j = idx & 63;
    int base = idx & ~63;
    int i = threadIdx.x;
    float sr = 0.f, si = 0.f;
    if (i != j) {
        float ljr = lam_re[idx], lji = lam_im[idx];
        float den = ljr * ljr + lji * lji;
        float lir = lam_re[base + i], lii = lam_im[base + i];
        float rr = (lir * ljr + lii * lji) / den;
        float ri = (lii * ljr - lir * lji) / den;
        float wr = 1.f - rr, wi = -ri;
        sr = 0.5f * logf(wr * wr + wi * wi);
        si = atan2f(wi, wr);
    }
    ssr[i] = sr; ssi[i] = si;
    __syncthreads();
    #pragma unroll
    for (int s = 32; s > 0; s >>= 1) {
        if (i < s) { ssr[i] += ssr[i + s]; ssi[i] += ssi[i + s]; }
        __syncthreads();
    }
    if (i == 0) {
        float er = expf(-ssr[0]);
        float sn, cs; sincosf(ssi[0], &sn, &cs);
        g_Bp[idx] = make_float2(er * cs, -er * sn);
    }
}

// ---------------- kernel 1b: B in fragment-major order, tf32 --------------
// slot id = (((kc*16 + nb)*2 + kp)*32 + lane)*4 + w
// value = Bstacked[n = nb*8 + (lane>>2)][gk = kc*32 + (2kp + (w>>1))*8 + (lane&3) + 4*(w&1)]
// Bstacked[n][gk]: p = gk>>1, q = gk&1, m = n&63:
//   n<64:  q0 -> C_re[p][m],  q1 -> -C_im[p][m]
//   n>=64: q0 -> C_im[p][m],  q1 ->  C_re[p][m]
__global__ void bprep_kernel(const float* __restrict__ C_re,
                             const float* __restrict__ C_im) {
    int id = blockIdx.x * 256 + threadIdx.x;   // 0..131071
    int w = id & 3;
    int lane = (id >> 2) & 31;
    int kp = (id >> 7) & 1;
    int nb = (id >> 8) & 15;
    int kc = id >> 12;
    int ks = 2 * kp + (w >> 1);
    int kloc = ks * 8 + (lane & 3) + 4 * (w & 1);
    int gk = kc * 32 + kloc;
    int p = gk >> 1, q = gk & 1;
    int n = nb * 8 + (lane >> 2);
    int m = n & 63;
    float v;
    if (n < 64) v = q ? -C_im[p * 64 + m] : C_re[p * 64 + m];
    else        v = q ?  C_re[p * 64 + m] : C_im[p * 64 + m];
    g_Bf[id] = f2tf32(v);
}

// ---------------- kernel 2: fused 3-pass scan, permuted tf32 output -------
__global__ __launch_bounds__(64) void scan_kernel(
        const float* __restrict__ x,
        const float* __restrict__ lam_re,
        const float* __restrict__ lam_im) {
    int bk = blockIdx.x;              // 0..255
    int b = bk >> 3;
    int k = bk & 7;
    int n = threadIdx.x;              // 0..63
    int kn = (k << 6) | n;

    float lr = lam_re[kn], li = lam_im[kn];
    float2 Bp = g_Bp[kn];
    float2 s1 = make_float2(0.f, 0.f);
    float2 s2 = make_float2(0.f, 0.f);
    float2 s3 = make_float2(0.f, 0.f);
    float p1r = 0.f, p1i = 0.f, p2r = 0.f, p2i = 0.f, p3r = 0.f, p3i = 0.f;
    float a1c = 1.f, a2c = 1.f;

    // permuted column indices (constants per thread):
    // original cols: re -> 2*(n&15), im -> re+1 within chunk kc = k*4 + (n>>4)
    int m_ = n & 15;
    int np_re = ((m_ >> 2) << 3) + ((m_ & 1) << 2) + ((m_ >> 1) & 1);
    int col_re = ((k << 2) + (n >> 4)) * 32 + np_re;
    int col_im = col_re + 2;

    __shared__ float xs[64];
    const int xoff = b * K_DIM + k;

    for (int tt = 0; tt < T_DIM; tt += 64) {
        __syncthreads();
        int tl = tt + n;
        xs[n] = (tl == 0) ? 0.f : x[(tl - 1) * BK + xoff];
        __syncthreads();
        #pragma unroll 8
        for (int j = 0; j < 64; ++j) {
            float xm1 = xs[j];
            float bxr = Bp.x * xm1, bxi = Bp.y * xm1;
            s3.x = fmaf(a2c, p3r, bxr);  s3.y = fmaf(a2c, p3i, bxi);
            s2.x = fmaf(a1c, p2r, bxr);  s2.y = fmaf(a1c, p2i, bxi);
            s1.x = p1r + bxr;            s1.y = p1i + bxi;
            p1r = lr * s1.x - li * s1.y;  p1i = lr * s1.y + li * s1.x;
            p2r = lr * s2.x - li * s2.y;  p2i = lr * s2.y + li * s2.x;
            p3r = lr * s3.x - li * s3.y;  p3i = lr * s3.y + li * s3.x;
            a1c = rsqrtf(1.f + p1r * p1r + p1i * p1i);
            a2c = rsqrtf(1.f + p2r * p2r + p2i * p2i);
            uint32_t ro = (((tt + j) << 5) + b) * 1024;
            g_Af[ro + col_re] = __uint_as_float(f2tf32(s3.x));
            g_Af[ro + col_im] = __uint_as_float(f2tf32(s3.y));
        }
    }
}

// ---------------- kernel 3: tf32 GEMM, 2 CTAs/SM, vector frag loads -------
// CTA 256 thr (8 warps, 4m x 2n), tile 128x128, warp tile 32x64.
// 3-stage cp.async, distance 2, 1 barrier per k32 chunk (R7-proven order).
#define SROWF 40                            // floats per A smem row (32+8 pad)
#define A_OFF 0
#define B_OFF (128 * SROWF * 4)             // 20480
#define STAGE_BYTES (B_OFF + 16384)         // 36864
#define NSTAGE 3
#define NCHUNK 32

extern __shared__ uint8_t dynSmem[];

__device__ __forceinline__ void issue_chunk(int kc, uint32_t sbuf, int rowBase,
                                            int tid) {
    const uint8_t* gA = (const uint8_t*)g_Af;
    const uint8_t* gB = (const uint8_t*)g_Bf;
    // A: 128 rows x 128B; thread -> (row = tid>>1, half = tid&1), 4x16B
    {
        int row = tid >> 1, half = tid & 1;
        size_t ga = (size_t)(rowBase + row) * 4096 + kc * 128 + half * 64;
        uint32_t so = sbuf + A_OFF + row * (SROWF * 4) + half * 64;
        #pragma unroll
        for (int i = 0; i < 4; ++i) CP16(so + i * 16, gA + ga + i * 16);
    }
    // B: contiguous 16KB block per chunk; thread -> 64B
    {
        size_t gb = (size_t)kc * 16384 + tid * 64;
        uint32_t so = sbuf + B_OFF + tid * 64;
        #pragma unroll
        for (int i = 0; i < 4; ++i) CP16(so + i * 16, gB + gb + i * 16);
    }
}

__global__ __launch_bounds__(256, 2) void gemm_mma(
        const float* __restrict__ x, const float* __restrict__ D,
        const float* __restrict__ Do, float* __restrict__ out, int writeCplx) {
    __shared__ float Ds[512];
    __shared__ float doSum[64];

    int tid = threadIdx.x;
    int wid = tid >> 5, lane = tid & 31;
    int wm = wid & 3, wn = wid >> 2;          // warp grid 4m x 2n
    int rowBase = blockIdx.x * 128;
    int gID = lane >> 2, tig = lane & 3;

    Ds[tid] = D[tid]; Ds[tid + 256] = D[tid + 256];
    if (tid < 64) {
        float s = 0.f;
        #pragma unroll
        for (int k = 0; k < K_DIM; ++k) s += Do[k * 64 + tid];
        doSum[tid] = s;
    }

    uint32_t sbase0 = smem_u32(dynSmem);

    float acc[2][8][4];
    #pragma unroll
    for (int mt = 0; mt < 2; ++mt)
        #pragma unroll
        for (int nt = 0; nt < 8; ++nt)
            #pragma unroll
            for (int e = 0; e < 4; ++e) acc[mt][nt][e] = 0.f;

    issue_chunk(0, sbase0, rowBase, tid);
    CP_COMMIT();
    issue_chunk(1, sbase0 + STAGE_BYTES, rowBase, tid);
    CP_COMMIT();

    int buf = 0;
    #pragma unroll 1
    for (int kc = 0; kc < NCHUNK; ++kc) {
        if (kc + 1 < NCHUNK) { CP_WAIT(1); } else { CP_WAIT(0); }
        __syncthreads();   // all threads: chunk kc landed; compute(kc-1) done
        if (kc + 2 < NCHUNK) {
            int nb = buf + 2; if (nb >= NSTAGE) nb -= NSTAGE;
            issue_chunk(kc + 2, sbase0 + nb * STAGE_BYTES, rowBase, tid);
            CP_COMMIT();
        }

        const uint8_t* base = dynSmem + buf * STAGE_BYTES;
        const float* sA = (const float*)(base + A_OFF);
        const uint4* sB4 = (const uint4*)(base + B_OFF);

        #pragma unroll
        for (int kp = 0; kp < 2; ++kp) {
            // B fragments: one LDS.128 per nt covers ks=2kp and 2kp+1
            uint4 bq[8];
            #pragma unroll
            for (int nt = 0; nt < 8; ++nt)
                bq[nt] = sB4[(((wn * 8 + nt) * 2 + kp) * 32) + lane];
            // A fragments: LDS.64 gives (kk, kk+4) adjacent (permuted layout)
            float2 a2v[2][2][2];   // [ksl][mt][rowhalf]
            #pragma unroll
            for (int ksl = 0; ksl < 2; ++ksl)
                #pragma unroll
                for (int mt = 0; mt < 2; ++mt) {
                    const float* ar = sA + (wm * 32 + mt * 16 + gID) * SROWF
                                    + (2 * kp + ksl) * 8 + 2 * tig;
                    a2v[ksl][mt][0] = *(const float2*)ar;
                    a2v[ksl][mt][1] = *(const float2*)(ar + 8 * SROWF);
                }
            #pragma unroll
            for (int ksl = 0; ksl < 2; ++ksl)
                #pragma unroll
                for (int nt = 0; nt < 8; ++nt)
                    #pragma unroll
                    for (int mt = 0; mt < 2; ++mt) {
                        uint32_t af[4];
                        af[0] = __float_as_uint(a2v[ksl][mt][0].x);
                        af[1] = __float_as_uint(a2v[ksl][mt][1].x);
                        af[2] = __float_as_uint(a2v[ksl][mt][0].y);
                        af[3] = __float_as_uint(a2v[ksl][mt][1].y);
                        mma_tf32(acc[mt][nt], af,
                                 ((const uint32_t*)&bq[nt]) + 2 * ksl);
                    }
        }
        ++buf; if (buf >= NSTAGE) buf = 0;
    }

    // epilogue (fragment layout: c0/c1 row gID, c2/c3 row gID+8)
    #pragma unroll
    for (int mt = 0; mt < 2; ++mt) {
        #pragma unroll
        for (int half = 0; half < 2; ++half) {
            int R = rowBase + wm * 32 + mt * 16 + gID + half * 8;
            float xv[K_DIM];
            #pragma unroll
            for (int k = 0; k < K_DIM; ++k) xv[k] = x[R * K_DIM + k];
            #pragma unroll
            for (int nt = 0; nt < 8; ++nt) {
                #pragma unroll
                for (int e = 0; e < 2; ++e) {
                    int col = wn * 64 + nt * 8 + tig * 2 + e;
                    float a = acc[mt][nt][half * 2 + e];
                    if (wn == 0) {  // real part: add x*D + Do, scale
                        int m = col;
                        float dt = doSum[m];
                        #pragma unroll
                        for (int k = 0; k < K_DIM; ++k)
                            dt = fmaf(xv[k], Ds[k * 64 + m], dt);
                        float v = (a + dt) * 0.125f;
                        if (writeCplx) out[((size_t)R * 64 + m) * 2] = v;
                        else           out[(size_t)R * 64 + m] = v;
                    } else {        // imag part
                        int m = col - 64;
                        if (writeCplx) out[((size_t)R * 64 + m) * 2 + 1] = a * 0.125f;
                    }
                }
            }
        }
    }
}

// ---------------- launch ----------------
extern "C" void kernel_launch(void* const* d_in, const int* in_sizes, int n_in,
                              void* d_out, int out_size) {
    const float* x = nullptr;
    const float* cbuf[2] = {nullptr, nullptr};
    const float* vbuf[4] = {nullptr, nullptr, nullptr, nullptr};
    int nc = 0, nv = 0;
    for (int i = 0; i < n_in; ++i) {
        int sz = in_sizes[i];
        const float* p = (const float*)d_in[i];
        if (sz == X_SZ) x = p;
        else if (sz == C_SZ) { if (nc < 2) cbuf[nc++] = p; }
        else if (sz == V_SZ) { if (nv < 4) vbuf[nv++] = p; }
    }
    if (!x || nc < 2 || nv < 4) return;
    const float* C_re   = cbuf[0];
    const float* C_im   = cbuf[1];
    const float* lam_re = vbuf[0];
    const float* lam_im = vbuf[1];
    const float* D      = vbuf[2];
    const float* Do     = vbuf[3];

    int writeCplx = (out_size >= 2 * OUT_CPLX) ? 1 : 0;

    cudaFuncSetAttribute(gemm_mma, cudaFuncAttributeMaxDynamicSharedMemorySize,
                         NSTAGE * STAGE_BYTES);

    bp_kernel<<<KN, 64>>>(lam_re, lam_im);
    bprep_kernel<<<512, 256>>>(C_re, C_im);
    scan_kernel<<<BK, N_DIM>>>(x, lam_re, lam_im);
    gemm_mma<<<ROWS / 128, 256, NSTAGE * STAGE_BYTES>>>(x, D, Do, (float*)d_out, writeCplx);
}

// round 12
// speedup vs baseline: 1.2585x; 1.2585x over previous
#include <cuda_runtime.h>
#include <cuda_fp16.h>
#include <cstdint>

// Problem dims (fixed by reference)
#define T_DIM 1024
#define B_DIM 32
#define K_DIM 8
#define N_DIM 64
#define M_DIM 64
#define KN    512      // K_DIM * N_DIM
#define BK    256      // B_DIM * K_DIM
#define ROWS  32768    // T*B rows of the big GEMM
#define KTOT  1024     // real K (re|im interleaved pairs; 512 uint32 per row)
#define NTOT  128      // output cols (re|im stacked)

#define X_SZ   (T_DIM * B_DIM * K_DIM)   // 262144
#define C_SZ   (K_DIM * N_DIM * M_DIM)   // 32768
#define V_SZ   (K_DIM * N_DIM)           // 512
#define OUT_CPLX (T_DIM * B_DIM * M_DIM) // 2097152 complex values

// A scaled by 1/16, B scaled by 16 (cancels exactly in the product).
#define A_SCALE 0.0625f
#define B_SCALE 16.0f

// ---------------- scratch (static device allocations only) ----------------
__device__ float2   g_Bp[KN];
__device__ uint32_t g_Ahi[(size_t)ROWS * 512];   // 64 MiB, packed f16x2 (re,im) hi
__device__ uint32_t g_Alo[(size_t)ROWS * 512];   // 64 MiB, f16x2 residual
__device__ uint32_t g_Bh[NTOT * 512];            // 256 KiB, [n][kk] K-major packed f16x2

// ---------------- PTX helpers (base sm_100 features only) ----------------
__device__ __forceinline__ uint32_t smem_u32(const void* p) {
    uint32_t a;
    asm("{ .reg .u64 t; cvta.to.shared.u64 t, %1; cvt.u32.u64 %0, t; }" : "=r"(a) : "l"(p));
    return a;
}
__device__ __forceinline__ void ldsm_x4(uint32_t* r, uint32_t addr) {
    asm volatile("ldmatrix.sync.aligned.m8n8.x4.shared.b16 {%0,%1,%2,%3}, [%4];"
                 : "=r"(r[0]), "=r"(r[1]), "=r"(r[2]), "=r"(r[3]) : "r"(addr));
}
__device__ __forceinline__ void mma_f16(float* d, const uint32_t* a, const uint32_t* b) {
    asm volatile("mma.sync.aligned.m16n8k16.row.col.f32.f16.f16.f32 "
                 "{%0,%1,%2,%3}, {%4,%5,%6,%7}, {%8,%9}, {%0,%1,%2,%3};"
                 : "+f"(d[0]), "+f"(d[1]), "+f"(d[2]), "+f"(d[3])
                 : "r"(a[0]), "r"(a[1]), "r"(a[2]), "r"(a[3]), "r"(b[0]), "r"(b[1]));
}
#define CP16(dst, src) \
    asm volatile("cp.async.cg.shared.global [%0], [%1], 16;" :: "r"(dst), "l"(src))
#define CP_COMMIT() asm volatile("cp.async.commit_group;" ::: "memory")
#define CP_WAIT(n)  asm volatile("cp.async.wait_group %0;" :: "n"(n) : "memory")

__device__ __forceinline__ uint32_t pack_f16x2(float lo, float hi) {
    __half2 h = __floats2half2_rn(lo, hi);   // lo -> low 16, hi -> high 16
    return *(uint32_t*)&h;
}

// ---------------- kernel 1: B' from lambda (fp32, parallel) ---------------
__global__ void bp_kernel(const float* __restrict__ lam_re,
                          const float* __restrict__ lam_im) {
    __shared__ float ssr[64], ssi[64];
    int idx = blockIdx.x;
    int j = idx & 63;
    int base = idx & ~63;
    int i = threadIdx.x;
    float sr = 0.f, si = 0.f;
    if (i != j) {
        float ljr = lam_re[idx], lji = lam_im[idx];
        float den = ljr * ljr + lji * lji;
        float lir = lam_re[base + i], lii = lam_im[base + i];
        float rr = (lir * ljr + lii * lji) / den;
        float ri = (lii * ljr - lir * lji) / den;
        float wr = 1.f - rr, wi = -ri;
        sr = 0.5f * logf(wr * wr + wi * wi);
        si = atan2f(wi, wr);
    }
    ssr[i] = sr; ssi[i] = si;
    __syncthreads();
    #pragma unroll
    for (int s = 32; s > 0; s >>= 1) {
        if (i < s) { ssr[i] += ssr[i + s]; ssi[i] += ssi[i + s]; }
        __syncthreads();
    }
    if (i == 0) {
        float er = expf(-ssr[0]);
        float sn, cs; sincosf(ssi[0], &sn, &cs);
        g_Bp[idx] = make_float2(er * cs, -er * sn);
    }
}

// ---------------- kernel 1b: stacked B (fp16, x16 scaled, packed pairs) ---
// B[n][2p]   : n<64 -> C_re[p][n],     n>=64 -> C_im[p][n-64]
// B[n][2p+1] : n<64 -> -C_im[p][n],    n>=64 -> C_re[p][n-64]
__global__ void bprep_kernel(const float* __restrict__ C_re,
                             const float* __restrict__ C_im) {
    int id = blockIdx.x * 256 + threadIdx.x;   // n*512 + p
    int n = id >> 9;
    int p = id & 511;
    int m = n & 63;
    float v0, v1;
    if (n < 64) { v0 = C_re[p * 64 + m]; v1 = -C_im[p * 64 + m]; }
    else        { v0 = C_im[p * 64 + m]; v1 =  C_re[p * 64 + m]; }
    g_Bh[id] = pack_f16x2(v0 * B_SCALE, v1 * B_SCALE);
}

// ---------------- kernel 2: fused 3-pass scan, fp16 hi/lo output ----------
// carry p = lam*s and a = rsqrt(1+|p|^2) computed at END of iteration t-1.
__global__ __launch_bounds__(64) void scan_kernel(
        const float* __restrict__ x,
        const float* __restrict__ lam_re,
        const float* __restrict__ lam_im) {
    int bk = blockIdx.x;              // 0..255
    int b = bk >> 3;
    int k = bk & 7;
    int n = threadIdx.x;              // 0..63
    int kn = (k << 6) | n;

    float lr = lam_re[kn], li = lam_im[kn];
    float2 Bp = g_Bp[kn];
    float2 s1 = make_float2(0.f, 0.f);
    float2 s2 = make_float2(0.f, 0.f);
    float2 s3 = make_float2(0.f, 0.f);
    float p1r = 0.f, p1i = 0.f, p2r = 0.f, p2i = 0.f, p3r = 0.f, p3i = 0.f;
    float a1c = 1.f, a2c = 1.f;

    __shared__ float xs[64];
    const int xoff = b * K_DIM + k;

    for (int tt = 0; tt < T_DIM; tt += 64) {
        __syncthreads();
        int tl = tt + n;
        xs[n] = (tl == 0) ? 0.f : x[(tl - 1) * BK + xoff];
        __syncthreads();
        #pragma unroll 8
        for (int j = 0; j < 64; ++j) {
            float xm1 = xs[j];
            float bxr = Bp.x * xm1, bxi = Bp.y * xm1;
            // state updates use CARRIED p (= lam*s_{t-1}) and alphas
            s3.x = fmaf(a2c, p3r, bxr);  s3.y = fmaf(a2c, p3i, bxi);
            s2.x = fmaf(a1c, p2r, bxr);  s2.y = fmaf(a1c, p2i, bxi);
            s1.x = p1r + bxr;            s1.y = p1i + bxi;
            // prepare next-step products and alphas (off critical path)
            p1r = lr * s1.x - li * s1.y;  p1i = lr * s1.y + li * s1.x;
            p2r = lr * s2.x - li * s2.y;  p2i = lr * s2.y + li * s2.x;
            p3r = lr * s3.x - li * s3.y;  p3i = lr * s3.y + li * s3.x;
            a1c = rsqrtf(1.f + p1r * p1r + p1i * p1i);
            a2c = rsqrtf(1.f + p2r * p2r + p2i * p2i);
            // emit fp16 hi/lo (scaled by 1/16)
            float ax = s3.x * A_SCALE, ay = s3.y * A_SCALE;
            __half2 h2 = __floats2half2_rn(ax, ay);
            float hx = __low2float(h2), hy = __high2float(h2);
            uint32_t ro = (((tt + j) << 5) + b) * 512 + kn;
            g_Ahi[ro] = *(uint32_t*)&h2;
            g_Alo[ro] = pack_f16x2(ax - hx, ay - hy);
        }
    }
}

// ---------------- kernel 3: mma.sync f16 GEMM, 2-pass, 3-stage ------------
// CTA 512 thr (16 warps, 8m x 2n), tile 256x128, warp tile 32x64.
// acc += Ah*Bh + Al*Bh per 32-wide k chunk (A hi/lo split; B hi only).
// Per chunk: CP_WAIT -> __syncthreads -> issue kc+2 -> compute kc (R7-proven).
#define SROW 80
#define AH_OFF 0
#define AL_OFF (256 * SROW)               // 20480
#define BH_OFF (2 * 256 * SROW)           // 40960
#define STAGE_BYTES (BH_OFF + 128 * SROW) // 51200
#define NSTAGE 3
#define NCHUNK 32

extern __shared__ uint8_t dynSmem[];

__device__ __forceinline__ void issue_chunk(int kc, uint32_t sbuf, int rowBase,
                                            int grow, int gc) {
    int k0b = kc * 64;   // byte offset of k32 chunk within a 2048B row
    const uint8_t* gAh = (const uint8_t*)g_Ahi;
    const uint8_t* gAl = (const uint8_t*)g_Alo;
    const uint8_t* gBh = (const uint8_t*)g_Bh;
    #pragma unroll
    for (int i = 0; i < 2; ++i) {
        int row = grow + i * 128;
        size_t ga = (size_t)(rowBase + row) * (KTOT * 2) + k0b + gc * 16;
        uint32_t so = row * SROW + gc * 16;
        CP16(sbuf + AH_OFF + so, gAh + ga);
        CP16(sbuf + AL_OFF + so, gAl + ga);
    }
    {
        size_t gb = (size_t)grow * (KTOT * 2) + k0b + gc * 16;
        uint32_t so = grow * SROW + gc * 16;
        CP16(sbuf + BH_OFF + so, gBh + gb);
    }
}

__global__ __launch_bounds__(512, 1) void gemm_mma(
        const float* __restrict__ x, const float* __restrict__ D,
        const float* __restrict__ Do, float* __restrict__ out, int writeCplx) {
    __shared__ float Ds[512];
    __shared__ float doSum[64];

    int tid = threadIdx.x;
    int wid = tid >> 5, lane = tid & 31;
    int wm = wid & 7, wn = wid >> 3;          // warp grid 8m x 2n
    int rowBase = blockIdx.x * 256;

    Ds[tid] = D[tid];
    if (tid < 64) {
        float s = 0.f;
        #pragma unroll
        for (int k = 0; k < K_DIM; ++k) s += Do[k * 64 + tid];
        doSum[tid] = s;
    }

    uint32_t sbase0 = smem_u32(dynSmem);

    // ldmatrix per-thread address components
    int mi = lane >> 3;                        // 0..3
    int arow = (lane & 7) + (mi & 1) * 8;
    int acol16 = mi >> 1;
    int bnrow = (mi >> 1) * 8 + (lane & 7);
    int bk16 = mi & 1;

    float acc[2][8][4];
    #pragma unroll
    for (int mt = 0; mt < 2; ++mt)
        #pragma unroll
        for (int nt = 0; nt < 8; ++nt)
            #pragma unroll
            for (int e = 0; e < 4; ++e) acc[mt][nt][e] = 0.f;

    int grow = tid >> 2, gc = tid & 3;         // grow 0..127

    issue_chunk(0, sbase0, rowBase, grow, gc);
    CP_COMMIT();
    issue_chunk(1, sbase0 + STAGE_BYTES, rowBase, grow, gc);
    CP_COMMIT();

    int buf = 0;                               // buffer index of chunk kc
    #pragma unroll 1
    for (int kc = 0; kc < NCHUNK; ++kc) {
        if (kc + 1 < NCHUNK) { CP_WAIT(1); } else { CP_WAIT(0); }
        __syncthreads();   // all threads: chunk kc landed; compute(kc-1) done
        if (kc + 2 < NCHUNK) {
            int nb = buf + 2; if (nb >= NSTAGE) nb -= NSTAGE;
            issue_chunk(kc + 2, sbase0 + nb * STAGE_BYTES, rowBase, grow, gc);
            CP_COMMIT();
        }

        uint32_t sAh = sbase0 + buf * STAGE_BYTES;
        uint32_t sAl = sAh + AL_OFF;
        uint32_t sBh = sAh + (BH_OFF - AH_OFF);

        #pragma unroll
        for (int ks = 0; ks < 2; ++ks) {
            uint32_t ah[2][4], al[2][4];
            #pragma unroll
            for (int mt = 0; mt < 2; ++mt) {
                uint32_t off = (wm * 32 + mt * 16 + arow) * SROW + ks * 32 + acol16 * 16;
                ldsm_x4(ah[mt], sAh + off);
                ldsm_x4(al[mt], sAl + off);
            }
            #pragma unroll
            for (int ntp = 0; ntp < 4; ++ntp) {
                uint32_t boff = (wn * 64 + ntp * 16 + bnrow) * SROW + ks * 32 + bk16 * 16;
                uint32_t bh4[4];
                ldsm_x4(bh4, sBh + boff);
                #pragma unroll
                for (int mt = 0; mt < 2; ++mt) {
                    mma_f16(acc[mt][2 * ntp],     ah[mt], bh4);
                    mma_f16(acc[mt][2 * ntp],     al[mt], bh4);
                    mma_f16(acc[mt][2 * ntp + 1], ah[mt], bh4 + 2);
                    mma_f16(acc[mt][2 * ntp + 1], al[mt], bh4 + 2);
                }
            }
        }
        ++buf; if (buf >= NSTAGE) buf = 0;
    }

    // epilogue (A_SCALE * B_SCALE = 1 -> no extra factor)
    int gID = lane >> 2, tg = lane & 3;
    #pragma unroll
    for (int mt = 0; mt < 2; ++mt) {
        #pragma unroll
        for (int half = 0; half < 2; ++half) {
            int R = rowBase + wm * 32 + mt * 16 + gID + half * 8;
            float xv[K_DIM];
            #pragma unroll
            for (int k = 0; k < K_DIM; ++k) xv[k] = x[R * K_DIM + k];
            #pragma unroll
            for (int nt = 0; nt < 8; ++nt) {
                #pragma unroll
                for (int e = 0; e < 2; ++e) {
                    int col = wn * 64 + nt * 8 + tg * 2 + e;
                    float a = acc[mt][nt][half * 2 + e];
                    if (wn == 0) {  // real part: add x*D + Do, scale by 1/8
                        int m = col;
                        float dt = doSum[m];
                        #pragma unroll
                        for (int k = 0; k < K_DIM; ++k)
                            dt = fmaf(xv[k], Ds[k * 64 + m], dt);
                        float v = (a + dt) * 0.125f;
                        if (writeCplx) out[((size_t)R * 64 + m) * 2] = v;
                        else           out[(size_t)R * 64 + m] = v;
                    } else {        // imag part
                        int m = col - 64;
                        if (writeCplx) out[((size_t)R * 64 + m) * 2 + 1] = a * 0.125f;
                    }
                }
            }
        }
    }
}

// ---------------- launch ----------------
extern "C" void kernel_launch(void* const* d_in, const int* in_sizes, int n_in,
                              void* d_out, int out_size) {
    const float* x = nullptr;
    const float* cbuf[2] = {nullptr, nullptr};
    const float* vbuf[4] = {nullptr, nullptr, nullptr, nullptr};
    int nc = 0, nv = 0;
    for (int i = 0; i < n_in; ++i) {
        int sz = in_sizes[i];
        const float* p = (const float*)d_in[i];
        if (sz == X_SZ) x = p;
        else if (sz == C_SZ) { if (nc < 2) cbuf[nc++] = p; }
        else if (sz == V_SZ) { if (nv < 4) vbuf[nv++] = p; }
    }
    if (!x || nc < 2 || nv < 4) return;
    const float* C_re   = cbuf[0];
    const float* C_im   = cbuf[1];
    const float* lam_re = vbuf[0];
    const float* lam_im = vbuf[1];
    const float* D      = vbuf[2];
    const float* Do     = vbuf[3];

    int writeCplx = (out_size >= 2 * OUT_CPLX) ? 1 : 0;

    cudaFuncSetAttribute(gemm_mma, cudaFuncAttributeMaxDynamicSharedMemorySize,
                         NSTAGE * STAGE_BYTES);

    bp_kernel<<<KN, 64>>>(lam_re, lam_im);
    bprep_kernel<<<NTOT * 512 / 256, 256>>>(C_re, C_im);
    scan_kernel<<<BK, N_DIM>>>(x, lam_re, lam_im);
    gemm_mma<<<ROWS / 256, 512, NSTAGE * STAGE_BYTES>>>(x, D, Do, (float*)d_out, writeCplx);
}

// round 13
// speedup vs baseline: 1.5243x; 1.2112x over previous
#include <cuda_runtime.h>
#include <cuda_fp16.h>
#include <cstdint>

// Problem dims (fixed by reference)
#define T_DIM 1024
#define B_DIM 32
#define K_DIM 8
#define N_DIM 64
#define M_DIM 64
#define KN    512      // K_DIM * N_DIM
#define BK    256      // B_DIM * K_DIM
#define ROWS  32768    // T*B rows of the big GEMM
#define KTOT  1024     // real K (re|im interleaved pairs; 512 uint32 per row)
#define NTOT  128      // output cols (re|im stacked)

#define X_SZ   (T_DIM * B_DIM * K_DIM)   // 262144
#define C_SZ   (K_DIM * N_DIM * M_DIM)   // 32768
#define V_SZ   (K_DIM * N_DIM)           // 512
#define OUT_CPLX (T_DIM * B_DIM * M_DIM) // 2097152 complex values

// A scaled by 1/16, B scaled by 16 (cancels exactly in the product).
#define A_SCALE 0.0625f
#define B_SCALE 16.0f

// ---------------- scratch (static device allocations only) ----------------
__device__ float2   g_Bp[KN];
__device__ uint32_t g_Ah[(size_t)ROWS * 512];    // 64 MiB, packed f16x2 (re,im)
__device__ uint32_t g_Bh[NTOT * 512];            // 256 KiB, [n][kk] K-major packed f16x2

// ---------------- PTX helpers (base sm_100 features only) ----------------
__device__ __forceinline__ uint32_t smem_u32(const void* p) {
    uint32_t a;
    asm("{ .reg .u64 t; cvta.to.shared.u64 t, %1; cvt.u32.u64 %0, t; }" : "=r"(a) : "l"(p));
    return a;
}
__device__ __forceinline__ void ldsm_x4(uint32_t* r, uint32_t addr) {
    asm volatile("ldmatrix.sync.aligned.m8n8.x4.shared.b16 {%0,%1,%2,%3}, [%4];"
                 : "=r"(r[0]), "=r"(r[1]), "=r"(r[2]), "=r"(r[3]) : "r"(addr));
}
__device__ __forceinline__ void mma_f16(float* d, const uint32_t* a, const uint32_t* b) {
    asm volatile("mma.sync.aligned.m16n8k16.row.col.f32.f16.f16.f32 "
                 "{%0,%1,%2,%3}, {%4,%5,%6,%7}, {%8,%9}, {%0,%1,%2,%3};"
                 : "+f"(d[0]), "+f"(d[1]), "+f"(d[2]), "+f"(d[3])
                 : "r"(a[0]), "r"(a[1]), "r"(a[2]), "r"(a[3]), "r"(b[0]), "r"(b[1]));
}
#define CP16(dst, src) \
    asm volatile("cp.async.cg.shared.global [%0], [%1], 16;" :: "r"(dst), "l"(src))
#define CP_COMMIT() asm volatile("cp.async.commit_group;" ::: "memory")
#define CP_WAIT(n)  asm volatile("cp.async.wait_group %0;" :: "n"(n) : "memory")

__device__ __forceinline__ uint32_t pack_f16x2(float lo, float hi) {
    __half2 h = __floats2half2_rn(lo, hi);   // lo -> low 16, hi -> high 16
    return *(uint32_t*)&h;
}

// ---------------- kernel 1: B' from lambda (fp32, parallel) ---------------
__global__ void bp_kernel(const float* __restrict__ lam_re,
                          const float* __restrict__ lam_im) {
    __shared__ float ssr[64], ssi[64];
    int idx = blockIdx.x;
    int j = idx & 63;
    int base = idx & ~63;
    int i = threadIdx.x;
    float sr = 0.f, si = 0.f;
    if (i != j) {
        float ljr = lam_re[idx], lji = lam_im[idx];
        float den = ljr * ljr + lji * lji;
        float lir = lam_re[base + i], lii = lam_im[base + i];
        float rr = (lir * ljr + lii * lji) / den;
        float ri = (lii * ljr - lir * lji) / den;
        float wr = 1.f - rr, wi = -ri;
        sr = 0.5f * logf(wr * wr + wi * wi);
        si = atan2f(wi, wr);
    }
    ssr[i] = sr; ssi[i] = si;
    __syncthreads();
    #pragma unroll
    for (int s = 32; s > 0; s >>= 1) {
        if (i < s) { ssr[i] += ssr[i + s]; ssi[i] += ssi[i + s]; }
        __syncthreads();
    }
    if (i == 0) {
        float er = expf(-ssr[0]);
        float sn, cs; sincosf(ssi[0], &sn, &cs);
        g_Bp[idx] = make_float2(er * cs, -er * sn);
    }
}

// ---------------- kernel 1b: stacked B (fp16, x16 scaled, packed pairs) ---
// B[n][2p]   : n<64 -> C_re[p][n],     n>=64 -> C_im[p][n-64]
// B[n][2p+1] : n<64 -> -C_im[p][n],    n>=64 -> C_re[p][n-64]
__global__ void bprep_kernel(const float* __restrict__ C_re,
                             const float* __restrict__ C_im) {
    int id = blockIdx.x * 256 + threadIdx.x;   // n*512 + p
    int n = id >> 9;
    int p = id & 511;
    int m = n & 63;
    float v0, v1;
    if (n < 64) { v0 = C_re[p * 64 + m]; v1 = -C_im[p * 64 + m]; }
    else        { v0 = C_im[p * 64 + m]; v1 =  C_re[p * 64 + m]; }
    g_Bh[id] = pack_f16x2(v0 * B_SCALE, v1 * B_SCALE);
}

// ---------------- kernel 2: fused 3-pass scan, fp16 output ----------------
// carry p = lam*s and a = rsqrt(1+|p|^2) computed at END of iteration t-1.
__global__ __launch_bounds__(64) void scan_kernel(
        const float* __restrict__ x,
        const float* __restrict__ lam_re,
        const float* __restrict__ lam_im) {
    int bk = blockIdx.x;              // 0..255
    int b = bk >> 3;
    int k = bk & 7;
    int n = threadIdx.x;              // 0..63
    int kn = (k << 6) | n;

    float lr = lam_re[kn], li = lam_im[kn];
    float2 Bp = g_Bp[kn];
    float2 s1 = make_float2(0.f, 0.f);
    float2 s2 = make_float2(0.f, 0.f);
    float2 s3 = make_float2(0.f, 0.f);
    float p1r = 0.f, p1i = 0.f, p2r = 0.f, p2i = 0.f, p3r = 0.f, p3i = 0.f;
    float a1c = 1.f, a2c = 1.f;

    __shared__ float xs[64];
    const int xoff = b * K_DIM + k;

    for (int tt = 0; tt < T_DIM; tt += 64) {
        __syncthreads();
        int tl = tt + n;
        xs[n] = (tl == 0) ? 0.f : x[(tl - 1) * BK + xoff];
        __syncthreads();
        #pragma unroll 8
        for (int j = 0; j < 64; ++j) {
            float xm1 = xs[j];
            float bxr = Bp.x * xm1, bxi = Bp.y * xm1;
            // state updates use CARRIED p (= lam*s_{t-1}) and alphas
            s3.x = fmaf(a2c, p3r, bxr);  s3.y = fmaf(a2c, p3i, bxi);
            s2.x = fmaf(a1c, p2r, bxr);  s2.y = fmaf(a1c, p2i, bxi);
            s1.x = p1r + bxr;            s1.y = p1i + bxi;
            // prepare next-step products and alphas (off critical path)
            p1r = lr * s1.x - li * s1.y;  p1i = lr * s1.y + li * s1.x;
            p2r = lr * s2.x - li * s2.y;  p2i = lr * s2.y + li * s2.x;
            p3r = lr * s3.x - li * s3.y;  p3i = lr * s3.y + li * s3.x;
            a1c = rsqrtf(1.f + p1r * p1r + p1i * p1i);
            a2c = rsqrtf(1.f + p2r * p2r + p2i * p2i);
            // emit fp16 (scaled by 1/16)
            uint32_t ro = (((tt + j) << 5) + b) * 512 + kn;
            g_Ah[ro] = pack_f16x2(s3.x * A_SCALE, s3.y * A_SCALE);
        }
    }
}

// ---------------- kernel 3: mma.sync f16 GEMM, single pass, 3-stage -------
// CTA 512 thr (16 warps, 8m x 2n), tile 256x128, warp tile 32x64.
// acc += A*B per 32-wide k chunk (single fp16 pass).
// Per chunk: CP_WAIT -> __syncthreads -> issue kc+2 -> compute kc (R7-proven).
#define SROW 80
#define AH_OFF 0
#define BH_OFF (256 * SROW)               // 20480
#define STAGE_BYTES (BH_OFF + 128 * SROW) // 30720
#define NSTAGE 3
#define NCHUNK 32

extern __shared__ uint8_t dynSmem[];

__device__ __forceinline__ void issue_chunk(int kc, uint32_t sbuf, int rowBase,
                                            int grow, int gc) {
    int k0b = kc * 64;   // byte offset of k32 chunk within a 2048B row
    const uint8_t* gAh = (const uint8_t*)g_Ah;
    const uint8_t* gBh = (const uint8_t*)g_Bh;
    #pragma unroll
    for (int i = 0; i < 2; ++i) {
        int row = grow + i * 128;
        size_t ga = (size_t)(rowBase + row) * (KTOT * 2) + k0b + gc * 16;
        uint32_t so = row * SROW + gc * 16;
        CP16(sbuf + AH_OFF + so, gAh + ga);
    }
    {
        size_t gb = (size_t)grow * (KTOT * 2) + k0b + gc * 16;
        uint32_t so = grow * SROW + gc * 16;
        CP16(sbuf + BH_OFF + so, gBh + gb);
    }
}

__global__ __launch_bounds__(512, 1) void gemm_mma(
        const float* __restrict__ x, const float* __restrict__ D,
        const float* __restrict__ Do, float* __restrict__ out, int writeCplx) {
    __shared__ float Ds[512];
    __shared__ float doSum[64];

    int tid = threadIdx.x;
    int wid = tid >> 5, lane = tid & 31;
    int wm = wid & 7, wn = wid >> 3;          // warp grid 8m x 2n
    int rowBase = blockIdx.x * 256;

    Ds[tid] = D[tid];
    if (tid < 64) {
        float s = 0.f;
        #pragma unroll
        for (int k = 0; k < K_DIM; ++k) s += Do[k * 64 + tid];
        doSum[tid] = s;
    }

    uint32_t sbase0 = smem_u32(dynSmem);

    // ldmatrix per-thread address components
    int mi = lane >> 3;                        // 0..3
    int arow = (lane & 7) + (mi & 1) * 8;
    int acol16 = mi >> 1;
    int bnrow = (mi >> 1) * 8 + (lane & 7);
    int bk16 = mi & 1;

    float acc[2][8][4];
    #pragma unroll
    for (int mt = 0; mt < 2; ++mt)
        #pragma unroll
        for (int nt = 0; nt < 8; ++nt)
            #pragma unroll
            for (int e = 0; e < 4; ++e) acc[mt][nt][e] = 0.f;

    int grow = tid >> 2, gc = tid & 3;         // grow 0..127

    issue_chunk(0, sbase0, rowBase, grow, gc);
    CP_COMMIT();
    issue_chunk(1, sbase0 + STAGE_BYTES, rowBase, grow, gc);
    CP_COMMIT();

    int buf = 0;                               // buffer index of chunk kc
    #pragma unroll 1
    for (int kc = 0; kc < NCHUNK; ++kc) {
        if (kc + 1 < NCHUNK) { CP_WAIT(1); } else { CP_WAIT(0); }
        __syncthreads();   // all threads: chunk kc landed; compute(kc-1) done
        if (kc + 2 < NCHUNK) {
            int nb = buf + 2; if (nb >= NSTAGE) nb -= NSTAGE;
            issue_chunk(kc + 2, sbase0 + nb * STAGE_BYTES, rowBase, grow, gc);
            CP_COMMIT();
        }

        uint32_t sAh = sbase0 + buf * STAGE_BYTES;
        uint32_t sBh = sAh + BH_OFF;

        #pragma unroll
        for (int ks = 0; ks < 2; ++ks) {
            uint32_t ah[2][4];
            #pragma unroll
            for (int mt = 0; mt < 2; ++mt) {
                uint32_t off = (wm * 32 + mt * 16 + arow) * SROW + ks * 32 + acol16 * 16;
                ldsm_x4(ah[mt], sAh + off);
            }
            #pragma unroll
            for (int ntp = 0; ntp < 4; ++ntp) {
                uint32_t boff = (wn * 64 + ntp * 16 + bnrow) * SROW + ks * 32 + bk16 * 16;
                uint32_t bh4[4];
                ldsm_x4(bh4, sBh + boff);
                #pragma unroll
                for (int mt = 0; mt < 2; ++mt) {
                    mma_f16(acc[mt][2 * ntp],     ah[mt], bh4);
                    mma_f16(acc[mt][2 * ntp + 1], ah[mt], bh4 + 2);
                }
            }
        }
        ++buf; if (buf >= NSTAGE) buf = 0;
    }

    // epilogue (A_SCALE * B_SCALE = 1 -> no extra factor)
    int gID = lane >> 2, tg = lane & 3;
    #pragma unroll
    for (int mt = 0; mt < 2; ++mt) {
        #pragma unroll
        for (int half = 0; half < 2; ++half) {
            int R = rowBase + wm * 32 + mt * 16 + gID + half * 8;
            float xv[K_DIM];
            #pragma unroll
            for (int k = 0; k < K_DIM; ++k) xv[k] = x[R * K_DIM + k];
            #pragma unroll
            for (int nt = 0; nt < 8; ++nt) {
                #pragma unroll
                for (int e = 0; e < 2; ++e) {
                    int col = wn * 64 + nt * 8 + tg * 2 + e;
                    float a = acc[mt][nt][half * 2 + e];
                    if (wn == 0) {  // real part: add x*D + Do, scale by 1/8
                        int m = col;
                        float dt = doSum[m];
                        #pragma unroll
                        for (int k = 0; k < K_DIM; ++k)
                            dt = fmaf(xv[k], Ds[k * 64 + m], dt);
                        float v = (a + dt) * 0.125f;
                        if (writeCplx) out[((size_t)R * 64 + m) * 2] = v;
                        else           out[(size_t)R * 64 + m] = v;
                    } else {        // imag part
                        int m = col - 64;
                        if (writeCplx) out[((size_t)R * 64 + m) * 2 + 1] = a * 0.125f;
                    }
                }
            }
        }
    }
}

// ---------------- launch ----------------
extern "C" void kernel_launch(void* const* d_in, const int* in_sizes, int n_in,
                              void* d_out, int out_size) {
    const float* x = nullptr;
    const float* cbuf[2] = {nullptr, nullptr};
    const float* vbuf[4] = {nullptr, nullptr, nullptr, nullptr};
    int nc = 0, nv = 0;
    for (int i = 0; i < n_in; ++i) {
        int sz = in_sizes[i];
        const float* p = (const float*)d_in[i];
        if (sz == X_SZ) x = p;
        else if (sz == C_SZ) { if (nc < 2) cbuf[nc++] = p; }
        else if (sz == V_SZ) { if (nv < 4) vbuf[nv++] = p; }
    }
    if (!x || nc < 2 || nv < 4) return;
    const float* C_re   = cbuf[0];
    const float* C_im   = cbuf[1];
    const float* lam_re = vbuf[0];
    const float* lam_im = vbuf[1];
    const float* D      = vbuf[2];
    const float* Do     = vbuf[3];

    int writeCplx = (out_size >= 2 * OUT_CPLX) ? 1 : 0;

    cudaFuncSetAttribute(gemm_mma, cudaFuncAttributeMaxDynamicSharedMemorySize,
                         NSTAGE * STAGE_BYTES);

    bp_kernel<<<KN, 64>>>(lam_re, lam_im);
    bprep_kernel<<<NTOT * 512 / 256, 256>>>(C_re, C_im);
    scan_kernel<<<BK, N_DIM>>>(x, lam_re, lam_im);
    gemm_mma<<<ROWS / 256, 512, NSTAGE * STAGE_BYTES>>>(x, D, Do, (float*)d_out, writeCplx);
}